// round 2
// baseline (speedup 1.0000x reference)
#include <cuda_runtime.h>
#include <math.h>

#define L   2048
#define DIM 1024
#define NH  16
#define KSZ 1024
#define VSZ 1024
#define HID 4096
#define HD  64

// ------------------------- scratch (device globals; no allocation) ---------
__device__ float g_tmp[(size_t)L * KSZ];
__device__ float g_q  [(size_t)L * KSZ];
__device__ float g_k  [(size_t)L * KSZ];
__device__ float g_v  [(size_t)L * VSZ];
__device__ float g_spb[(size_t)L * L];
__device__ float g_att[(size_t)NH * L * L];
__device__ float g_o  [(size_t)L * VSZ];
__device__ float g_o2 [(size_t)L * DIM];
__device__ float g_h  [(size_t)L * DIM];
__device__ float g_f1 [(size_t)L * HID];
__device__ float g_f2 [(size_t)L * DIM];

// ------------------------- generic tiled SGEMM (double-buffered) -----------
// C[M,N] = scale * (A[M,K] @ opB) + bias[N] + addmat[M,N]   (each term optional)
// opB = B[N,K]^T if TRANSB else B[K,N]
// BM=BN=128, BK=8, 256 threads, 8x8 micro-tile per thread.
// 2-stage smem double buffer with register staging: one __syncthreads per
// k-tile, global loads of tile t+1 overlap FFMAs of tile t.
// Assumes: M % 128 == 0, K % 8 == 0, N % 4 == 0 (true for all uses here).
template <bool TRANSB, bool RELU>
__global__ __launch_bounds__(256) void gemm_k(
    const float* __restrict__ A, int lda, long long sA,
    const float* __restrict__ B, int ldb, long long sB,
    float* __restrict__ C, int ldc, long long sC,
    const float* __restrict__ bias,
    const float* __restrict__ addmat, int ldam,
    float scale, int M, int N, int K)
{
    __shared__ float As[2][8][128];
    __shared__ float Bs[2][8][128];

    const int z = blockIdx.z;
    A += (long long)z * sA;
    B += (long long)z * sB;
    C += (long long)z * sC;

    const int m0 = blockIdx.y * 128;
    const int n0 = blockIdx.x * 128;
    const int tid = threadIdx.x;
    const int tx = tid & 15;      // 0..15  (cols)
    const int ty = tid >> 4;      // 0..15  (rows)

    // loader mapping (A and TRANSB-B): 128 rows x 8 k, one float4 along k per thread
    const int l_row = tid >> 1;         // 0..127
    const int l_kc  = (tid & 1) * 4;    // 0 or 4
    // loader mapping (non-trans B): 8 k x 128 n, one float4 along n per thread
    const int bk = tid >> 5;            // 0..7
    const int bn = (tid & 31) * 4;      // 0..124

    float acc[8][8];
#pragma unroll
    for (int i = 0; i < 8; i++)
#pragma unroll
        for (int j = 0; j < 8; j++) acc[i][j] = 0.f;

    const int T = K >> 3;   // number of 8-deep k-tiles

    // ---- helpers as lambdas (compile-time resolved) ----
    auto loadA = [&](int t) -> float4 {
        return *(const float4*)(A + (long long)(m0 + l_row) * lda + (t * 8 + l_kc));
    };
    auto loadB = [&](int t) -> float4 {
        if (TRANSB) {
            int n = n0 + l_row;
            if (n < N)
                return *(const float4*)(B + (long long)n * ldb + (t * 8 + l_kc));
            return make_float4(0.f, 0.f, 0.f, 0.f);
        } else {
            if (n0 + bn < N)
                return *(const float4*)(B + (long long)(t * 8 + bk) * ldb + (n0 + bn));
            return make_float4(0.f, 0.f, 0.f, 0.f);
        }
    };
    auto storeA = [&](int buf, float4 av) {
        As[buf][l_kc + 0][l_row] = av.x;
        As[buf][l_kc + 1][l_row] = av.y;
        As[buf][l_kc + 2][l_row] = av.z;
        As[buf][l_kc + 3][l_row] = av.w;
    };
    auto storeB = [&](int buf, float4 bv) {
        if (TRANSB) {
            Bs[buf][l_kc + 0][l_row] = bv.x;
            Bs[buf][l_kc + 1][l_row] = bv.y;
            Bs[buf][l_kc + 2][l_row] = bv.z;
            Bs[buf][l_kc + 3][l_row] = bv.w;
        } else {
            *(float4*)&Bs[buf][bk][bn] = bv;
        }
    };

    // ---- prologue: tile 0 into buffer 0 ----
    {
        float4 av = loadA(0);
        float4 bv = loadB(0);
        storeA(0, av);
        storeB(0, bv);
    }
    __syncthreads();

    // ---- mainloop ----
    for (int t = 0; t < T; t++) {
        const int buf = t & 1;
        float4 av, bv;
        const bool more = (t + 1 < T);
        if (more) {               // issue global loads for next tile early
            av = loadA(t + 1);
            bv = loadB(t + 1);
        }

#pragma unroll
        for (int kk = 0; kk < 8; kk++) {
            float a[8], b[8];
            *(float4*)&a[0] = *(const float4*)&As[buf][kk][ty * 4];
            *(float4*)&a[4] = *(const float4*)&As[buf][kk][64 + ty * 4];
            *(float4*)&b[0] = *(const float4*)&Bs[buf][kk][tx * 4];
            *(float4*)&b[4] = *(const float4*)&Bs[buf][kk][64 + tx * 4];
#pragma unroll
            for (int i = 0; i < 8; i++)
#pragma unroll
                for (int j = 0; j < 8; j++)
                    acc[i][j] += a[i] * b[j];
        }

        if (more) {
            storeA(buf ^ 1, av);  // target buffer was last READ in iter t-1;
            storeB(buf ^ 1, bv);  // the sync at end of t-1 made that safe
            __syncthreads();
        }
    }

    // ---- epilogue ----
#pragma unroll
    for (int i = 0; i < 8; i++) {
        int row = m0 + ((i < 4) ? (ty * 4 + i) : (64 + ty * 4 + (i - 4)));
#pragma unroll
        for (int jb = 0; jb < 2; jb++) {
            int col = n0 + jb * 64 + tx * 4;
            if (col < N) {
                float v0 = acc[i][jb * 4 + 0] * scale;
                float v1 = acc[i][jb * 4 + 1] * scale;
                float v2 = acc[i][jb * 4 + 2] * scale;
                float v3 = acc[i][jb * 4 + 3] * scale;
                if (bias) {
                    v0 += bias[col + 0]; v1 += bias[col + 1];
                    v2 += bias[col + 2]; v3 += bias[col + 3];
                }
                if (addmat) {
                    const float* am = addmat + (long long)row * ldam + col;
                    v0 += am[0]; v1 += am[1]; v2 += am[2]; v3 += am[3];
                }
                if (RELU) {
                    v0 = fmaxf(v0, 0.f); v1 = fmaxf(v1, 0.f);
                    v2 = fmaxf(v2, 0.f); v3 = fmaxf(v3, 0.f);
                }
                float4 outv = make_float4(v0, v1, v2, v3);
                *(float4*)(C + (long long)row * ldc + col) = outv;
            }
        }
    }
}

// ------------------------- block reductions --------------------------------
__device__ __forceinline__ float warp_sum(float v) {
#pragma unroll
    for (int o = 16; o; o >>= 1) v += __shfl_xor_sync(0xffffffffu, v, o);
    return v;
}
__device__ __forceinline__ float warp_max(float v) {
#pragma unroll
    for (int o = 16; o; o >>= 1) v = fmaxf(v, __shfl_xor_sync(0xffffffffu, v, o));
    return v;
}
__device__ __forceinline__ float block_sum(float v) {
    __shared__ float sh[8];
    int lane = threadIdx.x & 31, w = threadIdx.x >> 5;
    v = warp_sum(v);
    if (lane == 0) sh[w] = v;
    __syncthreads();
    if (w == 0) {
        float t = (lane < 8) ? sh[lane] : 0.f;
        t = warp_sum(t);
        if (lane == 0) sh[0] = t;
    }
    __syncthreads();
    float r = sh[0];
    __syncthreads();
    return r;
}
__device__ __forceinline__ float block_max(float v) {
    __shared__ float sh[8];
    int lane = threadIdx.x & 31, w = threadIdx.x >> 5;
    v = warp_max(v);
    if (lane == 0) sh[w] = v;
    __syncthreads();
    if (w == 0) {
        float t = (lane < 8) ? sh[lane] : -3.402823466e38f;
        t = warp_max(t);
        if (lane == 0) sh[0] = t;
    }
    __syncthreads();
    float r = sh[0];
    __syncthreads();
    return r;
}

// ------------------------- row softmax (ncols = 2048) ----------------------
// out[row] = softmax(in[row]) * postscale.  In-place safe.
__global__ __launch_bounds__(256) void softmax2048(
    const float* __restrict__ in, float* __restrict__ out, float postscale)
{
    long long row = blockIdx.x;
    const float* x = in + row * 2048;
    float* y = out + row * 2048;
    int tid = threadIdx.x;

    float r[8];
    float mx = -3.402823466e38f;
#pragma unroll
    for (int i = 0; i < 8; i++) {
        r[i] = x[i * 256 + tid];
        mx = fmaxf(mx, r[i]);
    }
    mx = block_max(mx);
    float s = 0.f;
#pragma unroll
    for (int i = 0; i < 8; i++) {
        r[i] = __expf(r[i] - mx);
        s += r[i];
    }
    s = block_sum(s);
    float inv = postscale / s;
#pragma unroll
    for (int i = 0; i < 8; i++) y[i * 256 + tid] = r[i] * inv;
}

// ------------------------- add + layernorm (ncols = 1024) ------------------
__global__ __launch_bounds__(256) void add_ln1024(
    const float* __restrict__ a, const float* __restrict__ b,
    const float* __restrict__ gamma, const float* __restrict__ beta,
    float* __restrict__ out)
{
    long long row = blockIdx.x;
    const float* pa = a + row * 1024;
    const float* pb = b + row * 1024;
    float* po = out + row * 1024;
    int tid = threadIdx.x;

    float r[4];
    float s = 0.f;
#pragma unroll
    for (int i = 0; i < 4; i++) {
        int idx = i * 256 + tid;
        r[i] = pa[idx] + pb[idx];
        s += r[i];
    }
    float mean = block_sum(s) * (1.f / 1024.f);
    float vs = 0.f;
#pragma unroll
    for (int i = 0; i < 4; i++) {
        float d = r[i] - mean;
        vs += d * d;
    }
    float var = block_sum(vs) * (1.f / 1024.f);
    float rs = rsqrtf(var + 1e-5f);
#pragma unroll
    for (int i = 0; i < 4; i++) {
        int idx = i * 256 + tid;
        po[idx] = (r[i] - mean) * rs * gamma[idx] + beta[idx];
    }
}

// ------------------------- host-side launch helper -------------------------
static inline void run_gemm(bool transb, bool relu,
    const float* A, int lda, long long sA,
    const float* B, int ldb, long long sB,
    float* C, int ldc, long long sC,
    const float* bias, const float* addmat, int ldam,
    float scale, int M, int N, int K, int batch)
{
    dim3 grid((N + 127) / 128, (M + 127) / 128, batch);
    if (transb) {
        if (relu) gemm_k<true, true><<<grid, 256>>>(A, lda, sA, B, ldb, sB, C, ldc, sC, bias, addmat, ldam, scale, M, N, K);
        else      gemm_k<true, false><<<grid, 256>>>(A, lda, sA, B, ldb, sB, C, ldc, sC, bias, addmat, ldam, scale, M, N, K);
    } else {
        if (relu) gemm_k<false, true><<<grid, 256>>>(A, lda, sA, B, ldb, sB, C, ldc, sC, bias, addmat, ldam, scale, M, N, K);
        else      gemm_k<false, false><<<grid, 256>>>(A, lda, sA, B, ldb, sB, C, ldc, sC, bias, addmat, ldam, scale, M, N, K);
    }
}

extern "C" void kernel_launch(void* const* d_in, const int* in_sizes, int n_in,
                              void* d_out, int out_size)
{
    const float* x   = (const float*)d_in[0];
    const float* sp  = (const float*)d_in[1];
    const float* Wq  = (const float*)d_in[2];  const float* bq  = (const float*)d_in[3];
    const float* Wk  = (const float*)d_in[4];  const float* bk  = (const float*)d_in[5];
    const float* Wv  = (const float*)d_in[6];  const float* bv  = (const float*)d_in[7];
    const float* Wqp = (const float*)d_in[8];  const float* bqp = (const float*)d_in[9];
    const float* Wkp = (const float*)d_in[10]; const float* bkp = (const float*)d_in[11];
    const float* Wvp = (const float*)d_in[12]; const float* bvp = (const float*)d_in[13];
    const float* Wo  = (const float*)d_in[14]; const float* bo  = (const float*)d_in[15];
    const float* W1  = (const float*)d_in[16]; const float* b1  = (const float*)d_in[17];
    const float* W2  = (const float*)d_in[18]; const float* b2  = (const float*)d_in[19];
    const float* g1  = (const float*)d_in[20]; const float* be1 = (const float*)d_in[21];
    const float* g2  = (const float*)d_in[22]; const float* be2 = (const float*)d_in[23];
    float* out = (float*)d_out;

    float *tmp, *q, *k, *v, *spb, *att, *o, *o2, *h, *f1, *f2;
    cudaGetSymbolAddress((void**)&tmp, g_tmp);
    cudaGetSymbolAddress((void**)&q,   g_q);
    cudaGetSymbolAddress((void**)&k,   g_k);
    cudaGetSymbolAddress((void**)&v,   g_v);
    cudaGetSymbolAddress((void**)&spb, g_spb);
    cudaGetSymbolAddress((void**)&att, g_att);
    cudaGetSymbolAddress((void**)&o,   g_o);
    cudaGetSymbolAddress((void**)&o2,  g_o2);
    cudaGetSymbolAddress((void**)&h,   g_h);
    cudaGetSymbolAddress((void**)&f1,  g_f1);
    cudaGetSymbolAddress((void**)&f2,  g_f2);

    // Q = (x@Wq^T+bq)@Wqp^T+bqp ; same for K, V
    run_gemm(true, false, x, DIM, 0, Wq, DIM, 0, tmp, KSZ, 0, bq, nullptr, 0, 1.f, L, KSZ, DIM, 1);
    run_gemm(true, false, tmp, KSZ, 0, Wqp, KSZ, 0, q, KSZ, 0, bqp, nullptr, 0, 1.f, L, KSZ, KSZ, 1);
    run_gemm(true, false, x, DIM, 0, Wk, DIM, 0, tmp, KSZ, 0, bk, nullptr, 0, 1.f, L, KSZ, DIM, 1);
    run_gemm(true, false, tmp, KSZ, 0, Wkp, KSZ, 0, k, KSZ, 0, bkp, nullptr, 0, 1.f, L, KSZ, KSZ, 1);
    run_gemm(true, false, x, DIM, 0, Wv, DIM, 0, tmp, VSZ, 0, bv, nullptr, 0, 1.f, L, VSZ, DIM, 1);
    run_gemm(true, false, tmp, VSZ, 0, Wvp, VSZ, 0, v, VSZ, 0, bvp, nullptr, 0, 1.f, L, VSZ, VSZ, 1);

    // spatial bias: softmax(shortest_path, axis=-1) * 0.5
    softmax2048<<<L, 256>>>(sp, spb, 0.5f);

    // att logits: per head, q_h @ k_h^T / 8 + spb  (batched over heads)
    run_gemm(true, false, q, KSZ, HD, k, KSZ, HD, att, L, (long long)L * L,
             nullptr, spb, L, 0.125f, L, L, HD, NH);

    // softmax over keys, in place
    softmax2048<<<NH * L, 256>>>(att, att, 1.f);

    // o_h = att_h @ v_h  (B non-transposed), interleaved head output
    run_gemm(false, false, att, L, (long long)L * L, v, VSZ, HD, o, VSZ, HD,
             nullptr, nullptr, 0, 1.f, L, HD, L, NH);

    // o2 = o @ Wo^T + bo
    run_gemm(true, false, o, VSZ, 0, Wo, VSZ, 0, o2, DIM, 0, bo, nullptr, 0, 1.f, L, DIM, VSZ, 1);

    // h = LN1(x + o2)
    add_ln1024<<<L, 256>>>(x, o2, g1, be1, h);

    // f = relu((relu(h@W1^T+b1))@W2^T+b2)
    run_gemm(true, true, h, DIM, 0, W1, DIM, 0, f1, HID, 0, b1, nullptr, 0, 1.f, L, HID, DIM, 1);
    run_gemm(true, true, f1, HID, 0, W2, HID, 0, f2, DIM, 0, b2, nullptr, 0, 1.f, L, DIM, HID, 1);

    // out = LN2(h + f)
    add_ln1024<<<L, 256>>>(h, f2, g2, be2, out);
}

// round 13
// speedup vs baseline: 2.4574x; 2.4574x over previous
#include <cuda_runtime.h>
#include <cuda.h>
#include <stdint.h>
#include <math.h>

#define L   2048
#define DIM 1024
#define NH  16
#define HD  64
#define HID 4096

// ------------------------- scratch (device globals; no allocation) ---------
__device__ float g_tmp[(size_t)L * DIM];
__device__ float g_q  [(size_t)L * DIM];
__device__ float g_k  [(size_t)L * DIM];
__device__ float g_v  [(size_t)L * DIM];
__device__ float g_vt [(size_t)DIM * L];          // transposed V: [1024][2048]
__device__ float g_spb[(size_t)L * L];
__device__ float g_att[(size_t)NH * L * L];
__device__ float g_o  [(size_t)L * DIM];
__device__ float g_o2 [(size_t)L * DIM];
__device__ float g_h  [(size_t)L * DIM];
__device__ float g_f1 [(size_t)L * HID];
__device__ float g_f2 [(size_t)L * DIM];

// ------------------------- helpers -----------------------------------------
__device__ __forceinline__ float to_tf32(float x) {
    uint32_t u;
    asm("cvt.rna.tf32.f32 %0, %1;" : "=r"(u) : "f"(x));
    return __uint_as_float(u);
}

#define MMA_TF32(d, a, b) \
    asm volatile("mma.sync.aligned.m16n8k8.row.col.f32.tf32.tf32.f32 " \
        "{%0,%1,%2,%3}, {%4,%5,%6,%7}, {%8,%9}, {%0,%1,%2,%3};" \
        : "+f"((d)[0]), "+f"((d)[1]), "+f"((d)[2]), "+f"((d)[3]) \
        : "r"((a)[0]), "r"((a)[1]), "r"((a)[2]), "r"((a)[3]), \
          "r"((b)[0]), "r"((b)[1]))

// ------------------------- tf32 mma.sync GEMM ------------------------------
// C[M,N] = scale * (A[M,K] @ B[N,K]^T) [+ bias[N]] [+ addmat[M,N]] [relu]
// CTA tile 128x128, BK=16, 256 threads (8 warps, 4(M) x 2(N)),
// warp tile 32x64 = 2x8 m16n8k8 fragments, double-buffered smem.
// M % 128 == 0, K % 16 == 0, N even; rows of B beyond N are zero-filled,
// C columns beyond N are not written.
template <bool RELU, bool ADDM>
__global__ __launch_bounds__(256) void gemm_mma(
    const float* __restrict__ A, int lda, long long sA,
    const float* __restrict__ B, int ldb, long long sB,
    float* __restrict__ C, int ldc, long long sC,
    const float* __restrict__ bias,
    const float* __restrict__ addmat, int ldam,
    float scale, int N, int K)
{
    __shared__ __align__(16) float As[2][128][20];
    __shared__ __align__(16) float Bs[2][128][20];

    A += (long long)blockIdx.z * sA;
    B += (long long)blockIdx.z * sB;
    C += (long long)blockIdx.z * sC;
    const int m0 = blockIdx.y * 128;
    const int n0 = blockIdx.x * 128;

    const int tid  = threadIdx.x;
    const int wid  = tid >> 5;
    const int lane = tid & 31;
    const int g    = lane >> 2;      // group id (0..7)
    const int tig  = lane & 3;       // thread in group (0..3)
    const int wm   = (wid & 3) * 32; // warp row base
    const int wn   = (wid >> 2) * 64;// warp col base

    // global loader mapping: idx in [0,512): row = idx>>2, kc = (idx&3)*4
    const int l_row = tid >> 2;          // rows 0..63 for it=0, +64 for it=1
    const int l_kc  = (tid & 3) * 4;

    auto ldgA = [&](int t, int it) -> float4 {
        const int row = l_row + it * 64;
        return *(const float4*)(A + (long long)(m0 + row) * lda + t * 16 + l_kc);
    };
    auto ldgB = [&](int t, int it) -> float4 {
        const int row = l_row + it * 64;
        if (n0 + row < N)
            return *(const float4*)(B + (long long)(n0 + row) * ldb + t * 16 + l_kc);
        return make_float4(0.f, 0.f, 0.f, 0.f);
    };
    auto stsA = [&](int buf, int it, float4 v) {
        const int row = l_row + it * 64;
        float4 c = make_float4(to_tf32(v.x), to_tf32(v.y), to_tf32(v.z), to_tf32(v.w));
        *(float4*)&As[buf][row][l_kc] = c;
    };
    auto stsB = [&](int buf, int it, float4 v) {
        const int row = l_row + it * 64;
        float4 c = make_float4(to_tf32(v.x), to_tf32(v.y), to_tf32(v.z), to_tf32(v.w));
        *(float4*)&Bs[buf][row][l_kc] = c;
    };

    float acc[2][8][4];
#pragma unroll
    for (int i = 0; i < 2; i++)
#pragma unroll
        for (int j = 0; j < 8; j++)
#pragma unroll
            for (int r = 0; r < 4; r++) acc[i][j][r] = 0.f;

    const int T = K >> 4;

    // prologue: tile 0 -> buffer 0
    {
        float4 a0 = ldgA(0, 0), a1 = ldgA(0, 1);
        float4 b0 = ldgB(0, 0), b1 = ldgB(0, 1);
        stsA(0, 0, a0); stsA(0, 1, a1);
        stsB(0, 0, b0); stsB(0, 1, b1);
    }
    __syncthreads();

    for (int t = 0; t < T; t++) {
        const int buf = t & 1;
        float4 a0, a1, b0, b1;
        const bool more = (t + 1 < T);
        if (more) {
            a0 = ldgA(t + 1, 0); a1 = ldgA(t + 1, 1);
            b0 = ldgB(t + 1, 0); b1 = ldgB(t + 1, 1);
        }

#pragma unroll
        for (int ks = 0; ks < 2; ks++) {
            const int kk = ks * 8;
            uint32_t af[2][4], bf[8][2];
#pragma unroll
            for (int i = 0; i < 2; i++) {
                const int m = wm + i * 16 + g;
                af[i][0] = __float_as_uint(As[buf][m    ][kk + tig]);
                af[i][1] = __float_as_uint(As[buf][m + 8][kk + tig]);
                af[i][2] = __float_as_uint(As[buf][m    ][kk + tig + 4]);
                af[i][3] = __float_as_uint(As[buf][m + 8][kk + tig + 4]);
            }
#pragma unroll
            for (int j = 0; j < 8; j++) {
                const int n = wn + j * 8 + g;
                bf[j][0] = __float_as_uint(Bs[buf][n][kk + tig]);
                bf[j][1] = __float_as_uint(Bs[buf][n][kk + tig + 4]);
            }
#pragma unroll
            for (int i = 0; i < 2; i++)
#pragma unroll
                for (int j = 0; j < 8; j++)
                    MMA_TF32(acc[i][j], af[i], bf[j]);
        }

        if (more) {
            stsA(buf ^ 1, 0, a0); stsA(buf ^ 1, 1, a1);
            stsB(buf ^ 1, 0, b0); stsB(buf ^ 1, 1, b1);
            __syncthreads();
        }
    }

    // ---- epilogue ----
#pragma unroll
    for (int i = 0; i < 2; i++) {
#pragma unroll
        for (int j = 0; j < 8; j++) {
            const int col = n0 + wn + j * 8 + 2 * tig;
            if (col >= N) continue;
            const int row = m0 + wm + i * 16 + g;
            float bb0 = 0.f, bb1 = 0.f;
            if (bias) { bb0 = bias[col]; bb1 = bias[col + 1]; }

            float v0 = acc[i][j][0] * scale + bb0;
            float v1 = acc[i][j][1] * scale + bb1;
            if (ADDM) {
                const float* am = addmat + (long long)row * ldam + col;
                v0 += am[0]; v1 += am[1];
            }
            if (RELU) { v0 = fmaxf(v0, 0.f); v1 = fmaxf(v1, 0.f); }
            *(float2*)(C + (long long)row * ldc + col) = make_float2(v0, v1);

            const int row2 = row + 8;
            float v2 = acc[i][j][2] * scale + bb0;
            float v3 = acc[i][j][3] * scale + bb1;
            if (ADDM) {
                const float* am = addmat + (long long)row2 * ldam + col;
                v2 += am[0]; v3 += am[1];
            }
            if (RELU) { v2 = fmaxf(v2, 0.f); v3 = fmaxf(v3, 0.f); }
            *(float2*)(C + (long long)row2 * ldc + col) = make_float2(v2, v3);
        }
    }
}

// ------------------------- V transpose: v[2048][1024] -> vt[1024][2048] ----
__global__ __launch_bounds__(256) void transpose_k(
    const float* __restrict__ src, float* __restrict__ dst)
{
    __shared__ float t[32][33];
    const int bx = blockIdx.x * 32;   // src col
    const int by = blockIdx.y * 32;   // src row
    const int x = threadIdx.x, y = threadIdx.y;
#pragma unroll
    for (int i = 0; i < 32; i += 8)
        t[y + i][x] = src[(long long)(by + y + i) * DIM + bx + x];
    __syncthreads();
#pragma unroll
    for (int i = 0; i < 32; i += 8)
        dst[(long long)(bx + y + i) * L + by + x] = t[x][y + i];
}

// ------------------------- block reductions --------------------------------
__device__ __forceinline__ float warp_sum(float v) {
#pragma unroll
    for (int o = 16; o; o >>= 1) v += __shfl_xor_sync(0xffffffffu, v, o);
    return v;
}
__device__ __forceinline__ float warp_max(float v) {
#pragma unroll
    for (int o = 16; o; o >>= 1) v = fmaxf(v, __shfl_xor_sync(0xffffffffu, v, o));
    return v;
}
__device__ __forceinline__ float block_sum(float v) {
    __shared__ float sh[8];
    int lane = threadIdx.x & 31, w = threadIdx.x >> 5;
    v = warp_sum(v);
    if (lane == 0) sh[w] = v;
    __syncthreads();
    if (w == 0) {
        float t = (lane < 8) ? sh[lane] : 0.f;
        t = warp_sum(t);
        if (lane == 0) sh[0] = t;
    }
    __syncthreads();
    float r = sh[0];
    __syncthreads();
    return r;
}
__device__ __forceinline__ float block_max(float v) {
    __shared__ float sh[8];
    int lane = threadIdx.x & 31, w = threadIdx.x >> 5;
    v = warp_max(v);
    if (lane == 0) sh[w] = v;
    __syncthreads();
    if (w == 0) {
        float t = (lane < 8) ? sh[lane] : -3.402823466e38f;
        t = warp_max(t);
        if (lane == 0) sh[0] = t;
    }
    __syncthreads();
    float r = sh[0];
    __syncthreads();
    return r;
}

// ------------------------- row softmax (2048 cols) -------------------------
__global__ __launch_bounds__(256) void softmax2048(
    const float* __restrict__ in, float* __restrict__ out, float postscale)
{
    long long row = blockIdx.x;
    const float* x = in + row * 2048;
    float* y = out + row * 2048;
    int tid = threadIdx.x;

    float r[8];
    float mx = -3.402823466e38f;
#pragma unroll
    for (int i = 0; i < 8; i++) {
        r[i] = x[i * 256 + tid];
        mx = fmaxf(mx, r[i]);
    }
    mx = block_max(mx);
    float s = 0.f;
#pragma unroll
    for (int i = 0; i < 8; i++) {
        r[i] = __expf(r[i] - mx);
        s += r[i];
    }
    s = block_sum(s);
    float inv = postscale / s;
#pragma unroll
    for (int i = 0; i < 8; i++) y[i * 256 + tid] = r[i] * inv;
}

// ------------------------- add + layernorm (1024 cols) ---------------------
__global__ __launch_bounds__(256) void add_ln1024(
    const float* __restrict__ a, const float* __restrict__ b,
    const float* __restrict__ gamma, const float* __restrict__ beta,
    float* __restrict__ out)
{
    long long row = blockIdx.x;
    const float* pa = a + row * 1024;
    const float* pb = b + row * 1024;
    float* po = out + row * 1024;
    int tid = threadIdx.x;

    float r[4];
    float s = 0.f;
#pragma unroll
    for (int i = 0; i < 4; i++) {
        int idx = i * 256 + tid;
        r[i] = pa[idx] + pb[idx];
        s += r[i];
    }
    float mean = block_sum(s) * (1.f / 1024.f);
    float vs = 0.f;
#pragma unroll
    for (int i = 0; i < 4; i++) {
        float d = r[i] - mean;
        vs += d * d;
    }
    float var = block_sum(vs) * (1.f / 1024.f);
    float rs = rsqrtf(var + 1e-5f);
#pragma unroll
    for (int i = 0; i < 4; i++) {
        int idx = i * 256 + tid;
        po[idx] = (r[i] - mean) * rs * gamma[idx] + beta[idx];
    }
}

// ------------------------- host side ---------------------------------------
template <bool RELU, bool ADDM>
static inline void launch_gemm(
    const float* A, int lda, long long sA,
    const float* B, int ldb, long long sB,
    float* C, int ldc, long long sC,
    const float* bias, const float* addmat, int ldam,
    float scale, int M, int N, int K, int batch)
{
    dim3 grid((N + 127) / 128, M / 128, batch);
    gemm_mma<RELU, ADDM><<<grid, 256>>>(
        A, lda, sA, B, ldb, sB, C, ldc, sC, bias, addmat, ldam, scale, N, K);
}

extern "C" void kernel_launch(void* const* d_in, const int* in_sizes, int n_in,
                              void* d_out, int out_size)
{
    const float* x   = (const float*)d_in[0];
    const float* sp  = (const float*)d_in[1];
    const float* Wq  = (const float*)d_in[2];  const float* bq  = (const float*)d_in[3];
    const float* Wk  = (const float*)d_in[4];  const float* bk  = (const float*)d_in[5];
    const float* Wv  = (const float*)d_in[6];  const float* bv  = (const float*)d_in[7];
    const float* Wqp = (const float*)d_in[8];  const float* bqp = (const float*)d_in[9];
    const float* Wkp = (const float*)d_in[10]; const float* bkp = (const float*)d_in[11];
    const float* Wvp = (const float*)d_in[12]; const float* bvp = (const float*)d_in[13];
    const float* Wo  = (const float*)d_in[14]; const float* bo  = (const float*)d_in[15];
    const float* W1  = (const float*)d_in[16]; const float* b1  = (const float*)d_in[17];
    const float* W2  = (const float*)d_in[18]; const float* b2  = (const float*)d_in[19];
    const float* g1  = (const float*)d_in[20]; const float* be1 = (const float*)d_in[21];
    const float* g2  = (const float*)d_in[22]; const float* be2 = (const float*)d_in[23];
    float* out = (float*)d_out;

    float *tmp, *q, *k, *v, *vt, *spb, *att, *o, *o2, *h, *f1, *f2;
    cudaGetSymbolAddress((void**)&tmp, g_tmp);
    cudaGetSymbolAddress((void**)&q,   g_q);
    cudaGetSymbolAddress((void**)&k,   g_k);
    cudaGetSymbolAddress((void**)&v,   g_v);
    cudaGetSymbolAddress((void**)&vt,  g_vt);
    cudaGetSymbolAddress((void**)&spb, g_spb);
    cudaGetSymbolAddress((void**)&att, g_att);
    cudaGetSymbolAddress((void**)&o,   g_o);
    cudaGetSymbolAddress((void**)&o2,  g_o2);
    cudaGetSymbolAddress((void**)&h,   g_h);
    cudaGetSymbolAddress((void**)&f1,  g_f1);
    cudaGetSymbolAddress((void**)&f2,  g_f2);

    // Q/K/V double projections (C = A @ W^T + b)
    launch_gemm<false, false>(x,   DIM, 0, Wq,  DIM, 0, tmp, DIM, 0, bq,  nullptr, 0, 1.f, L, DIM, DIM, 1);
    launch_gemm<false, false>(tmp, DIM, 0, Wqp, DIM, 0, q,   DIM, 0, bqp, nullptr, 0, 1.f, L, DIM, DIM, 1);
    launch_gemm<false, false>(x,   DIM, 0, Wk,  DIM, 0, tmp, DIM, 0, bk,  nullptr, 0, 1.f, L, DIM, DIM, 1);
    launch_gemm<false, false>(tmp, DIM, 0, Wkp, DIM, 0, k,   DIM, 0, bkp, nullptr, 0, 1.f, L, DIM, DIM, 1);
    launch_gemm<false, false>(x,   DIM, 0, Wv,  DIM, 0, tmp, DIM, 0, bv,  nullptr, 0, 1.f, L, DIM, DIM, 1);
    launch_gemm<false, false>(tmp, DIM, 0, Wvp, DIM, 0, v,   DIM, 0, bvp, nullptr, 0, 1.f, L, DIM, DIM, 1);

    // vt[c][k] = v[k][c]
    transpose_k<<<dim3(DIM / 32, L / 32), dim3(32, 8)>>>(v, vt);

    // spatial bias: softmax(shortest_path) * 0.5
    softmax2048<<<L, 256>>>(sp, spb, 0.5f);

    // att = q_h @ k_h^T / 8 + spb   (batched over heads via grid.z; K=64)
    launch_gemm<false, true>(q, DIM, HD, k, DIM, HD, att, L, (long long)L * L,
                             nullptr, spb, L, 0.125f, L, L, HD, NH);

    // softmax over keys, in place
    softmax2048<<<NH * L, 256>>>(att, att, 1.f);

    // o_h = att_h @ v_h: A = att [L, L], B = vt_h [64, L] (K-major via transpose)
    launch_gemm<false, false>(att, L, (long long)L * L, vt, L, (long long)HD * L,
                              o, DIM, HD, nullptr, nullptr, 0, 1.f, L, HD, L, NH);

    // o2 = o @ Wo^T + bo
    launch_gemm<false, false>(o, DIM, 0, Wo, DIM, 0, o2, DIM, 0, bo, nullptr, 0, 1.f, L, DIM, DIM, 1);

    // h = LN1(x + o2)
    add_ln1024<<<L, 256>>>(x, o2, g1, be1, h);

    // f = relu((relu(h@W1^T+b1))@W2^T+b2)
    launch_gemm<true, false>(h,  DIM, 0, W1, DIM, 0, f1, HID, 0, b1, nullptr, 0, 1.f, L, HID, DIM, 1);
    launch_gemm<true, false>(f1, HID, 0, W2, HID, 0, f2, DIM, 0, b2, nullptr, 0, 1.f, L, DIM, HID, 1);

    // out = LN2(h + f)
    add_ln1024<<<L, 256>>>(h, f2, g2, be2, out);
}

// round 14
// speedup vs baseline: 2.9186x; 1.1877x over previous
#include <cuda_runtime.h>
#include <cuda.h>
#include <stdint.h>
#include <math.h>

#define L   2048
#define DIM 1024
#define NH  16
#define HD  64
#define HID 4096
#define NS  3       // cp.async pipeline stages
#define BK  16

// ------------------------- scratch (device globals; no allocation) ---------
__device__ float g_tmp[(size_t)L * DIM];
__device__ float g_q  [(size_t)L * DIM];
__device__ float g_k  [(size_t)L * DIM];
__device__ float g_v  [(size_t)L * DIM];
__device__ float g_vt [(size_t)DIM * L];          // transposed V: [1024][2048]
__device__ float g_spb[(size_t)L * L];
__device__ float g_att[(size_t)NH * L * L];
__device__ float g_o  [(size_t)L * DIM];
__device__ float g_o2 [(size_t)L * DIM];
__device__ float g_h  [(size_t)L * DIM];
__device__ float g_f1 [(size_t)L * HID];
__device__ float g_f2 [(size_t)L * DIM];

// ------------------------- helpers -----------------------------------------
__device__ __forceinline__ uint32_t smem_u32(const void* p) {
    uint32_t a;
    asm("{ .reg .u64 t; cvta.to.shared.u64 t, %1; cvt.u32.u64 %0, t; }" : "=r"(a) : "l"(p));
    return a;
}
__device__ __forceinline__ void cp_async16(uint32_t s, const void* g) {
    asm volatile("cp.async.cg.shared.global [%0], [%1], 16;" :: "r"(s), "l"(g));
}

#define MMA_TF32(d, a, b) \
    asm volatile("mma.sync.aligned.m16n8k8.row.col.f32.tf32.tf32.f32 " \
        "{%0,%1,%2,%3}, {%4,%5,%6,%7}, {%8,%9}, {%0,%1,%2,%3};" \
        : "+f"((d)[0]), "+f"((d)[1]), "+f"((d)[2]), "+f"((d)[3]) \
        : "r"((a)[0]), "r"((a)[1]), "r"((a)[2]), "r"((a)[3]), \
          "r"((b)[0]), "r"((b)[1]))

// ------------------------- tf32 mma.sync GEMM ------------------------------
// C[M,N] = scale * (A[M,K] @ B[N,K]^T) [+ bias[N]] [+ addmat[M,N]] [relu]
// CTA tile 128x64, BK=16, 256 threads (8 warps, 4(M) x 2(N)),
// warp tile 32x32 = 2x4 m16n8k8 fragments, 3-stage cp.async pipeline.
// M % 128 == 0, N % 64 == 0, K % 16 == 0.
// tf32 via truncation (raw fp32 bits into tf32 mma operands).
template <bool RELU, bool ADDM>
__global__ __launch_bounds__(256) void gemm_mma(
    const float* __restrict__ A, int lda, long long sA,
    const float* __restrict__ B, int ldb, long long sB,
    float* __restrict__ C, int ldc, long long sC,
    const float* __restrict__ bias,
    const float* __restrict__ addmat, int ldam,
    float scale, int N, int K)
{
    __shared__ __align__(16) float As[NS][128][20];
    __shared__ __align__(16) float Bs[NS][64][20];

    A += (long long)blockIdx.z * sA;
    B += (long long)blockIdx.z * sB;
    C += (long long)blockIdx.z * sC;
    const int m0 = blockIdx.y * 128;
    const int n0 = blockIdx.x * 64;

    const int tid  = threadIdx.x;
    const int wid  = tid >> 5;
    const int lane = tid & 31;
    const int g    = lane >> 2;      // group id (0..7)
    const int tig  = lane & 3;       // thread in group (0..3)
    const int wm   = (wid & 3) * 32; // warp row base
    const int wn   = (wid >> 2) * 32;// warp col base

    // loader mapping: row = tid>>2 (0..63), kc = (tid&3)*4
    const int l_row = tid >> 2;
    const int l_kc  = (tid & 3) * 4;

    const int T = K >> 4;

    auto issue = [&](int t) {
        if (t < T) {
            const int buf = t % NS;
            const int k0 = t * BK + l_kc;
            cp_async16(smem_u32(&As[buf][l_row][l_kc]),
                       A + (long long)(m0 + l_row) * lda + k0);
            cp_async16(smem_u32(&As[buf][l_row + 64][l_kc]),
                       A + (long long)(m0 + l_row + 64) * lda + k0);
            cp_async16(smem_u32(&Bs[buf][l_row][l_kc]),
                       B + (long long)(n0 + l_row) * ldb + k0);
        }
        asm volatile("cp.async.commit_group;" ::: "memory");
    };

    float acc[2][4][4];
#pragma unroll
    for (int i = 0; i < 2; i++)
#pragma unroll
        for (int j = 0; j < 4; j++)
#pragma unroll
            for (int r = 0; r < 4; r++) acc[i][j][r] = 0.f;

    // prologue: stages 0, 1 in flight
    issue(0);
    issue(1);

    for (int t = 0; t < T; t++) {
        asm volatile("cp.async.wait_group 1;" ::: "memory");
        __syncthreads();

        issue(t + 2);   // into buf (t+2)%NS == (t-1)%NS, safe after sync

        const int buf = t % NS;
#pragma unroll
        for (int ks = 0; ks < 2; ks++) {
            const int kk = ks * 8;
            uint32_t af[2][4], bf[4][2];
#pragma unroll
            for (int i = 0; i < 2; i++) {
                const int m = wm + i * 16 + g;
                af[i][0] = __float_as_uint(As[buf][m    ][kk + tig]);
                af[i][1] = __float_as_uint(As[buf][m + 8][kk + tig]);
                af[i][2] = __float_as_uint(As[buf][m    ][kk + tig + 4]);
                af[i][3] = __float_as_uint(As[buf][m + 8][kk + tig + 4]);
            }
#pragma unroll
            for (int j = 0; j < 4; j++) {
                const int n = wn + j * 8 + g;
                bf[j][0] = __float_as_uint(Bs[buf][n][kk + tig]);
                bf[j][1] = __float_as_uint(Bs[buf][n][kk + tig + 4]);
            }
#pragma unroll
            for (int i = 0; i < 2; i++)
#pragma unroll
                for (int j = 0; j < 4; j++)
                    MMA_TF32(acc[i][j], af[i], bf[j]);
        }
    }

    // ---- epilogue ----
#pragma unroll
    for (int i = 0; i < 2; i++) {
#pragma unroll
        for (int j = 0; j < 4; j++) {
            const int col = n0 + wn + j * 8 + 2 * tig;
            const int row = m0 + wm + i * 16 + g;
            float bb0 = 0.f, bb1 = 0.f;
            if (bias) { bb0 = bias[col]; bb1 = bias[col + 1]; }

            float v0 = acc[i][j][0] * scale + bb0;
            float v1 = acc[i][j][1] * scale + bb1;
            if (ADDM) {
                const float* am = addmat + (long long)row * ldam + col;
                v0 += am[0]; v1 += am[1];
            }
            if (RELU) { v0 = fmaxf(v0, 0.f); v1 = fmaxf(v1, 0.f); }
            *(float2*)(C + (long long)row * ldc + col) = make_float2(v0, v1);

            const int row2 = row + 8;
            float v2 = acc[i][j][2] * scale + bb0;
            float v3 = acc[i][j][3] * scale + bb1;
            if (ADDM) {
                const float* am = addmat + (long long)row2 * ldam + col;
                v2 += am[0]; v3 += am[1];
            }
            if (RELU) { v2 = fmaxf(v2, 0.f); v3 = fmaxf(v3, 0.f); }
            *(float2*)(C + (long long)row2 * ldc + col) = make_float2(v2, v3);
        }
    }
}

// ------------------------- V transpose: v[2048][1024] -> vt[1024][2048] ----
__global__ __launch_bounds__(256) void transpose_k(
    const float* __restrict__ src, float* __restrict__ dst)
{
    __shared__ float t[32][33];
    const int bx = blockIdx.x * 32;   // src col
    const int by = blockIdx.y * 32;   // src row
    const int x = threadIdx.x, y = threadIdx.y;
#pragma unroll
    for (int i = 0; i < 32; i += 8)
        t[y + i][x] = src[(long long)(by + y + i) * DIM + bx + x];
    __syncthreads();
#pragma unroll
    for (int i = 0; i < 32; i += 8)
        dst[(long long)(bx + y + i) * L + by + x] = t[x][y + i];
}

// ------------------------- block reductions --------------------------------
__device__ __forceinline__ float warp_sum(float v) {
#pragma unroll
    for (int o = 16; o; o >>= 1) v += __shfl_xor_sync(0xffffffffu, v, o);
    return v;
}
__device__ __forceinline__ float warp_max(float v) {
#pragma unroll
    for (int o = 16; o; o >>= 1) v = fmaxf(v, __shfl_xor_sync(0xffffffffu, v, o));
    return v;
}
__device__ __forceinline__ float block_sum(float v) {
    __shared__ float sh[8];
    int lane = threadIdx.x & 31, w = threadIdx.x >> 5;
    v = warp_sum(v);
    if (lane == 0) sh[w] = v;
    __syncthreads();
    if (w == 0) {
        float t = (lane < 8) ? sh[lane] : 0.f;
        t = warp_sum(t);
        if (lane == 0) sh[0] = t;
    }
    __syncthreads();
    float r = sh[0];
    __syncthreads();
    return r;
}
__device__ __forceinline__ float block_max(float v) {
    __shared__ float sh[8];
    int lane = threadIdx.x & 31, w = threadIdx.x >> 5;
    v = warp_max(v);
    if (lane == 0) sh[w] = v;
    __syncthreads();
    if (w == 0) {
        float t = (lane < 8) ? sh[lane] : -3.402823466e38f;
        t = warp_max(t);
        if (lane == 0) sh[0] = t;
    }
    __syncthreads();
    float r = sh[0];
    __syncthreads();
    return r;
}

// ------------------------- row softmax (2048 cols) -------------------------
__global__ __launch_bounds__(256) void softmax2048(
    const float* __restrict__ in, float* __restrict__ out, float postscale)
{
    long long row = blockIdx.x;
    const float* x = in + row * 2048;
    float* y = out + row * 2048;
    int tid = threadIdx.x;

    float r[8];
    float mx = -3.402823466e38f;
#pragma unroll
    for (int i = 0; i < 8; i++) {
        r[i] = x[i * 256 + tid];
        mx = fmaxf(mx, r[i]);
    }
    mx = block_max(mx);
    float s = 0.f;
#pragma unroll
    for (int i = 0; i < 8; i++) {
        r[i] = __expf(r[i] - mx);
        s += r[i];
    }
    s = block_sum(s);
    float inv = postscale / s;
#pragma unroll
    for (int i = 0; i < 8; i++) y[i * 256 + tid] = r[i] * inv;
}

// ------------------------- add + layernorm (1024 cols) ---------------------
__global__ __launch_bounds__(256) void add_ln1024(
    const float* __restrict__ a, const float* __restrict__ b,
    const float* __restrict__ gamma, const float* __restrict__ beta,
    float* __restrict__ out)
{
    long long row = blockIdx.x;
    const float* pa = a + row * 1024;
    const float* pb = b + row * 1024;
    float* po = out + row * 1024;
    int tid = threadIdx.x;

    float r[4];
    float s = 0.f;
#pragma unroll
    for (int i = 0; i < 4; i++) {
        int idx = i * 256 + tid;
        r[i] = pa[idx] + pb[idx];
        s += r[i];
    }
    float mean = block_sum(s) * (1.f / 1024.f);
    float vs = 0.f;
#pragma unroll
    for (int i = 0; i < 4; i++) {
        float d = r[i] - mean;
        vs += d * d;
    }
    float var = block_sum(vs) * (1.f / 1024.f);
    float rs = rsqrtf(var + 1e-5f);
#pragma unroll
    for (int i = 0; i < 4; i++) {
        int idx = i * 256 + tid;
        po[idx] = (r[i] - mean) * rs * gamma[idx] + beta[idx];
    }
}

// ------------------------- host side ---------------------------------------
template <bool RELU, bool ADDM>
static inline void launch_gemm(
    const float* A, int lda, long long sA,
    const float* B, int ldb, long long sB,
    float* C, int ldc, long long sC,
    const float* bias, const float* addmat, int ldam,
    float scale, int M, int N, int K, int batch)
{
    dim3 grid(N / 64, M / 128, batch);
    gemm_mma<RELU, ADDM><<<grid, 256>>>(
        A, lda, sA, B, ldb, sB, C, ldc, sC, bias, addmat, ldam, scale, N, K);
}

extern "C" void kernel_launch(void* const* d_in, const int* in_sizes, int n_in,
                              void* d_out, int out_size)
{
    const float* x   = (const float*)d_in[0];
    const float* sp  = (const float*)d_in[1];
    const float* Wq  = (const float*)d_in[2];  const float* bq  = (const float*)d_in[3];
    const float* Wk  = (const float*)d_in[4];  const float* bk  = (const float*)d_in[5];
    const float* Wv  = (const float*)d_in[6];  const float* bv  = (const float*)d_in[7];
    const float* Wqp = (const float*)d_in[8];  const float* bqp = (const float*)d_in[9];
    const float* Wkp = (const float*)d_in[10]; const float* bkp = (const float*)d_in[11];
    const float* Wvp = (const float*)d_in[12]; const float* bvp = (const float*)d_in[13];
    const float* Wo  = (const float*)d_in[14]; const float* bo  = (const float*)d_in[15];
    const float* W1  = (const float*)d_in[16]; const float* b1  = (const float*)d_in[17];
    const float* W2  = (const float*)d_in[18]; const float* b2  = (const float*)d_in[19];
    const float* g1  = (const float*)d_in[20]; const float* be1 = (const float*)d_in[21];
    const float* g2  = (const float*)d_in[22]; const float* be2 = (const float*)d_in[23];
    float* out = (float*)d_out;

    float *tmp, *q, *k, *v, *vt, *spb, *att, *o, *o2, *h, *f1, *f2;
    cudaGetSymbolAddress((void**)&tmp, g_tmp);
    cudaGetSymbolAddress((void**)&q,   g_q);
    cudaGetSymbolAddress((void**)&k,   g_k);
    cudaGetSymbolAddress((void**)&v,   g_v);
    cudaGetSymbolAddress((void**)&vt,  g_vt);
    cudaGetSymbolAddress((void**)&spb, g_spb);
    cudaGetSymbolAddress((void**)&att, g_att);
    cudaGetSymbolAddress((void**)&o,   g_o);
    cudaGetSymbolAddress((void**)&o2,  g_o2);
    cudaGetSymbolAddress((void**)&h,   g_h);
    cudaGetSymbolAddress((void**)&f1,  g_f1);
    cudaGetSymbolAddress((void**)&f2,  g_f2);

    // Q/K/V double projections (C = A @ W^T + b)
    launch_gemm<false, false>(x,   DIM, 0, Wq,  DIM, 0, tmp, DIM, 0, bq,  nullptr, 0, 1.f, L, DIM, DIM, 1);
    launch_gemm<false, false>(tmp, DIM, 0, Wqp, DIM, 0, q,   DIM, 0, bqp, nullptr, 0, 1.f, L, DIM, DIM, 1);
    launch_gemm<false, false>(x,   DIM, 0, Wk,  DIM, 0, tmp, DIM, 0, bk,  nullptr, 0, 1.f, L, DIM, DIM, 1);
    launch_gemm<false, false>(tmp, DIM, 0, Wkp, DIM, 0, k,   DIM, 0, bkp, nullptr, 0, 1.f, L, DIM, DIM, 1);
    launch_gemm<false, false>(x,   DIM, 0, Wv,  DIM, 0, tmp, DIM, 0, bv,  nullptr, 0, 1.f, L, DIM, DIM, 1);
    launch_gemm<false, false>(tmp, DIM, 0, Wvp, DIM, 0, v,   DIM, 0, bvp, nullptr, 0, 1.f, L, DIM, DIM, 1);

    // vt[c][k] = v[k][c]
    transpose_k<<<dim3(DIM / 32, L / 32), dim3(32, 8)>>>(v, vt);

    // spatial bias: softmax(shortest_path) * 0.5
    softmax2048<<<L, 256>>>(sp, spb, 0.5f);

    // att = q_h @ k_h^T / 8 + spb   (batched over heads via grid.z; K=64)
    launch_gemm<false, true>(q, DIM, HD, k, DIM, HD, att, L, (long long)L * L,
                             nullptr, spb, L, 0.125f, L, L, HD, NH);

    // softmax over keys, in place
    softmax2048<<<NH * L, 256>>>(att, att, 1.f);

    // o_h = att_h @ v_h: A = att [L, L], B = vt_h [64, L] (K-major via transpose)
    launch_gemm<false, false>(att, L, (long long)L * L, vt, L, (long long)HD * L,
                              o, DIM, HD, nullptr, nullptr, 0, 1.f, L, HD, L, NH);

    // o2 = o @ Wo^T + bo
    launch_gemm<false, false>(o, DIM, 0, Wo, DIM, 0, o2, DIM, 0, bo, nullptr, 0, 1.f, L, DIM, DIM, 1);

    // h = LN1(x + o2)
    add_ln1024<<<L, 256>>>(x, o2, g1, be1, h);

    // f = relu((relu(h@W1^T+b1))@W2^T+b2)
    launch_gemm<true, false>(h,  DIM, 0, W1, DIM, 0, f1, HID, 0, b1, nullptr, 0, 1.f, L, HID, DIM, 1);
    launch_gemm<true, false>(f1, HID, 0, W2, HID, 0, f2, DIM, 0, b2, nullptr, 0, 1.f, L, DIM, HID, 1);

    // out = LN2(h + f)
    add_ln1024<<<L, 256>>>(h, f2, g2, be2, out);
}